// round 16
// baseline (speedup 1.0000x reference)
#include <cuda_runtime.h>
#include <cuda_bf16.h>
#include <math_constants.h>

#define N_NODES 50000
#define N_EDGES 800000
#define NODE_DIM 64
#define EDGE_DIM 32
#define IN_DIM   160
#define OUT_F    64
#define WROW     164

#define SCAN_BLK 512
#define SCAN_NBLK ((N_NODES + SCAN_BLK - 1) / SCAN_BLK)   // 98
#define NODE_BLKS ((N_NODES + 7) / 8)                     // 6250
#define EDGE_BLKS (((size_t)N_EDGES * 4 + 255) / 256)     // 12500

// ---------------- static scratch (g_cnt kept zero between runs) ----------------
__device__ float g_pd[N_NODES];
__device__ float2 g_pdo[N_NODES];       // (pd, off-as-bits) packed for fill2
__device__ float2 g_sr[N_NODES];        // (sum exp(qe+pd) per src, h.wa[0:64])
__device__ int   g_cnt[N_NODES];        // ALWAYS zero at kernel_launch entry
__device__ int   g_off[N_NODES + 1];
__device__ int   g_aux[SCAN_NBLK];

__device__ float2 g_qt [N_EDGES];       // (ef.wg[0:32], ef.wa[64:96]) edge order
__device__ int    g_rank[N_EDGES];      // rank within dst segment (from histogram)
__device__ float4 g_meta[N_EDGES];      // (exp(qe+pd), te, src, eid) dst-sorted

// ---------------- packed f32x2 helpers ----------------
__device__ __forceinline__ unsigned long long fma2(unsigned long long a,
                                                   unsigned long long b,
                                                   unsigned long long c) {
    unsigned long long d;
    asm("fma.rn.f32x2 %0, %1, %2, %3;" : "=l"(d) : "l"(a), "l"(b), "l"(c));
    return d;
}
__device__ __forceinline__ unsigned long long pack2(float x, float y) {
    unsigned long long r;
    asm("mov.b64 %0, {%1, %2};" : "=l"(r) : "f"(x), "f"(y));
    return r;
}
__device__ __forceinline__ float2 unpack2(unsigned long long v) {
    float2 r;
    asm("mov.b64 {%0, %1}, %2;" : "=f"(r.x), "=f"(r.y) : "l"(v));
    return r;
}

// ---------------- K1: node dots+init ∥ ef dots + histogram/rank ------------
__global__ void k_heavy(const float* __restrict__ h,
                        const float* __restrict__ ef,
                        const float* __restrict__ wg,
                        const float* __restrict__ wa,
                        const int* __restrict__ dst) {
    if (blockIdx.x < NODE_BLKS) {
        int node = blockIdx.x * 8 + (threadIdx.x >> 5);
        int lane = threadIdx.x & 31;
        if (node >= N_NODES) return;
        const float* hp = h + (size_t)node * NODE_DIM;
        float v0 = hp[lane];
        float v1 = hp[lane + 32];
        float pd = v0 * wg[96 + lane]  + v1 * wg[128 + lane];
        float r  = v0 * wa[lane]       + v1 * wa[32 + lane];
        #pragma unroll
        for (int o = 16; o; o >>= 1) {
            pd += __shfl_xor_sync(0xffffffffu, pd, o);
            r  += __shfl_xor_sync(0xffffffffu, r,  o);
        }
        if (lane == 0) {
            g_pd[node] = pd;
            g_sr[node] = make_float2(0.0f, r);
        }
    } else {
        int gid = (int)((blockIdx.x - NODE_BLKS) * blockDim.x + threadIdx.x);
        int e = gid >> 2;
        int k = gid & 3;
        if (e >= N_EDGES) return;
        float4 v0 = ((const float4*)ef)[(size_t)e * 8 + k];
        float4 v1 = ((const float4*)ef)[(size_t)e * 8 + k + 4];
        float4 a0 = ((const float4*)wg)[k];
        float4 a1 = ((const float4*)wg)[k + 4];
        float4 b0 = ((const float4*)wa)[16 + k];
        float4 b1 = ((const float4*)wa)[20 + k];
        float qe = v0.x * a0.x + v0.y * a0.y + v0.z * a0.z + v0.w * a0.w
                 + v1.x * a1.x + v1.y * a1.y + v1.z * a1.z + v1.w * a1.w;
        float te = v0.x * b0.x + v0.y * b0.y + v0.z * b0.z + v0.w * b0.w
                 + v1.x * b1.x + v1.y * b1.y + v1.z * b1.z + v1.w * b1.w;
        qe += __shfl_xor_sync(0xffffffffu, qe, 2);
        te += __shfl_xor_sync(0xffffffffu, te, 2);
        qe += __shfl_xor_sync(0xffffffffu, qe, 1);
        te += __shfl_xor_sync(0xffffffffu, te, 1);
        if (k == 0) {
            g_qt[e] = make_float2(qe, te);
            g_rank[e] = atomicAdd(&g_cnt[dst[e]], 1);   // rank within dst segment
        }
    }
}

// ---------------- K2a: per-block scan (zeroes g_cnt after reading) ---------
__global__ void k_scan1() {
    __shared__ int sh[SCAN_BLK];
    int tid = threadIdx.x;
    int i = blockIdx.x * SCAN_BLK + tid;
    int v = 0;
    if (i < N_NODES) {
        v = g_cnt[i];
        g_cnt[i] = 0;          // restore the zero invariant for the next run
    }
    sh[tid] = v;
    __syncthreads();
    #pragma unroll
    for (int off = 1; off < SCAN_BLK; off <<= 1) {
        int t = (tid >= off) ? sh[tid - off] : 0;
        __syncthreads();
        sh[tid] += t;
        __syncthreads();
    }
    if (i < N_NODES) g_off[i] = sh[tid] - v;
    if (tid == SCAN_BLK - 1) g_aux[blockIdx.x] = sh[tid];
}

// ---------------- K2b: aux prefix + final offsets + packed (pd,off) --------
__global__ void k_scan23() {
    __shared__ int s_aux[SCAN_NBLK];
    __shared__ int s_base;
    int tid = threadIdx.x;
    if (tid < SCAN_NBLK) s_aux[tid] = g_aux[tid];
    __syncthreads();
    if (tid == 0) {
        int run = 0;
        for (int b = 0; b < blockIdx.x; b++) run += s_aux[b];
        s_base = run;
    }
    __syncthreads();
    int i = blockIdx.x * SCAN_BLK + tid;
    if (i < N_NODES) {
        int o = g_off[i] + s_base;
        g_off[i] = o;
        g_pdo[i] = make_float2(g_pd[i], __int_as_float(o));
    }
    if (i == 0) g_off[N_NODES] = N_EDGES;
}

// ---------------- K3: light fill — 2 edges/thread, rank-based slots --------
__global__ void k_fill2(const int* __restrict__ src,
                        const int* __restrict__ dst) {
    int t = blockIdx.x * blockDim.x + threadIdx.x;
    int e0 = t * 2;
    if (e0 >= N_EDGES) return;
    float4 qt2 = ((const float4*)g_qt)[t];
    int2 s2 = ((const int2*)src)[t];
    int2 d2 = ((const int2*)dst)[t];
    int2 r2 = ((const int2*)g_rank)[t];
    float2 pdo0 = g_pdo[d2.x];              // ONE random sector: pd + off
    float2 pdo1 = g_pdo[d2.y];
    float ee0 = __expf(qt2.x + pdo0.x);
    float ee1 = __expf(qt2.z + pdo1.x);
    atomicAdd(&g_sr[s2.x].x, ee0);
    atomicAdd(&g_sr[s2.y].x, ee1);
    int p0 = __float_as_int(pdo0.y) + r2.x;  // no atomic: precomputed rank
    int p1 = __float_as_int(pdo1.y) + r2.y;
    g_meta[p0] = make_float4(ee0, qt2.y, __int_as_float(s2.x), __int_as_float(e0));
    g_meta[p1] = make_float4(ee1, qt2.w, __int_as_float(s2.y), __int_as_float(e0 + 1));
}

// ---------------- K4: gather (2 nodes/warp) + GEMV, 4 blocks/SM ------------
__global__ void __launch_bounds__(256, 4) k_gather_out(
        const float* __restrict__ h,
        const float* __restrict__ ef,
        const float* __restrict__ wlin,
        float* __restrict__ out) {
    extern __shared__ __align__(16) float smem[];
    float*  s_wT   = smem;                                  // [64][WROW] 42KB
    float*  s_hc   = smem + OUT_F * WROW;                   // [8][2][160] 10KB
    float4* s_meta = (float4*)(s_hc + 8 * 2 * IN_DIM);      // [8][32] 4KB

    int tid  = threadIdx.x;
    int warp = tid >> 5;
    int lane = tid & 31;
    int grp  = lane >> 4;       // 0/1: which edge of each 2-pack
    int hl   = lane & 15;       // position within 16-lane group

    for (int i = tid; i < IN_DIM * OUT_F; i += blockDim.x) {
        int k = i >> 6, c = i & 63;
        s_wT[c * WROW + k] = wlin[i];
    }
    __syncthreads();

    const ulonglong2*        h128 = (const ulonglong2*)h;           // 16 per row
    const unsigned long long* e64 = (const unsigned long long*)ef;  // 16 per row
    float*  hcW = s_hc + warp * (2 * IN_DIM);
    float4* mW  = s_meta + warp * 32;

    int gwarp  = blockIdx.x * 8 + warp;
    int nwarps = gridDim.x * 8;

    for (int g0 = gwarp * 2; g0 < N_NODES; g0 += nwarps * 2) {
        #pragma unroll
        for (int nn = 0; nn < 2; nn++) {
            int node = g0 + nn;
            if (node >= N_NODES) break;
            int beg = g_off[node];
            int end = g_off[node + 1];

            unsigned long long accHa = 0, accHb = 0;  // dims 4hl..4hl+3 (group partial)
            unsigned long long accE2 = 0;             // dims 2hl..2hl+1 (group partial)
            float se = 0.0f;

            for (int base = beg; base < end; base += 32) {
                int i = base + lane;
                if (i < end) {
                    float4 m4  = g_meta[i];         // contiguous LDG.128
                    int sidx   = __float_as_int(m4.z);
                    float2 sr  = g_sr[sidx];        // random, L2-resident
                    float gamma = m4.x / sr.x;
                    float w = __expf(sr.y + gamma * m4.y);
                    se += w;
                    mW[lane] = make_float4(w, w * gamma, m4.z, m4.w);
                }
                __syncwarp();
                int cnt  = min(32, end - base);
                int half = (cnt + 1) >> 1;
                #pragma unroll 8
                for (int t = 0; t < half; t++) {
                    int j = 2 * t + grp;
                    if (j < cnt) {
                        float4 m = mW[j];
                        int s  = __float_as_int(m.z);
                        int ej = __float_as_int(m.w);
                        ulonglong2 hv = __ldg(&h128[(size_t)s * 16 + hl]);   // LDG.128
                        unsigned long long ev = __ldg(&e64[(size_t)ej * 16 + hl]); // LDG.64
                        unsigned long long wpp = pack2(m.x, m.x);
                        accHa = fma2(wpp, hv.x, accHa);
                        accHb = fma2(wpp, hv.y, accHb);
                        accE2 = fma2(pack2(m.y, m.y), ev, accE2);
                    }
                }
                __syncwarp();
            }

            // reduce se over full warp
            #pragma unroll
            for (int o = 16; o; o >>= 1)
                se += __shfl_xor_sync(0xffffffffu, se, o);
            float inv = (end > beg) ? 1.0f / se : 0.0f;

            // combine the two 16-lane group partials
            float2 pa = unpack2(accHa), qa = unpack2(__shfl_xor_sync(0xffffffffu, accHa, 16));
            float2 pb = unpack2(accHb), qb = unpack2(__shfl_xor_sync(0xffffffffu, accHb, 16));
            float2 pe = unpack2(accE2), qe = unpack2(__shfl_xor_sync(0xffffffffu, accE2, 16));

            float* hc = hcW + nn * IN_DIM;
            float2 own = ((const float2*)h)[(size_t)node * 32 + lane];
            ((float2*)hc)[lane] = own;                                  // dims 0..63
            if (lane < 16) {
                ((float4*)(hc + 64))[hl] = make_float4((pa.x + qa.x) * inv,
                                                       (pa.y + qa.y) * inv,
                                                       (pb.x + qb.x) * inv,
                                                       (pb.y + qb.y) * inv); // 64..127
                ((float2*)(hc + 128))[hl] = make_float2((pe.x + qe.x) * inv,
                                                        (pe.y + qe.y) * inv); // 128..159
            }
        }
        __syncwarp();

        // ---- 2-node GEMV with packed FFMA2 ----
        unsigned long long aA[2][2] = {};
        unsigned long long aB[2][2] = {};
        const ulonglong2* wA = (const ulonglong2*)&s_wT[lane * WROW];
        const ulonglong2* wB = (const ulonglong2*)&s_wT[(lane + 32) * WROW];
        const ulonglong2* hv0 = (const ulonglong2*)(hcW + 0 * IN_DIM);
        const ulonglong2* hv1 = (const ulonglong2*)(hcW + 1 * IN_DIM);

        #pragma unroll 4
        for (int q = 0; q < IN_DIM / 4; q++) {
            ulonglong2 va = wA[q];
            ulonglong2 vb = wB[q];
            ulonglong2 x0 = hv0[q], x1 = hv1[q];
            aA[0][0] = fma2(va.x, x0.x, aA[0][0]); aA[0][1] = fma2(va.y, x0.y, aA[0][1]);
            aA[1][0] = fma2(va.x, x1.x, aA[1][0]); aA[1][1] = fma2(va.y, x1.y, aA[1][1]);
            aB[0][0] = fma2(vb.x, x0.x, aB[0][0]); aB[0][1] = fma2(vb.y, x0.y, aB[0][1]);
            aB[1][0] = fma2(vb.x, x1.x, aB[1][0]); aB[1][1] = fma2(vb.y, x1.y, aB[1][1]);
        }

        #pragma unroll
        for (int nn = 0; nn < 2; nn++) {
            int node = g0 + nn;
            if (node >= N_NODES) break;
            float2 uA0 = unpack2(aA[nn][0]), uA1 = unpack2(aA[nn][1]);
            float2 uB0 = unpack2(aB[nn][0]), uB1 = unpack2(aB[nn][1]);
            float oA = (uA0.x + uA0.y) + (uA1.x + uA1.y);
            float oB = (uB0.x + uB0.y) + (uB1.x + uB1.y);
            out[(size_t)node * OUT_F + lane]      = fmaxf(oA, 0.f);
            out[(size_t)node * OUT_F + 32 + lane] = fmaxf(oB, 0.f);
        }
        __syncwarp();
    }
}

// ---------------- launcher ----------------
extern "C" void kernel_launch(void* const* d_in, const int* in_sizes, int n_in,
                              void* d_out, int out_size) {
    const float* h   = (const float*)d_in[0];
    const float* ef  = (const float*)d_in[1];
    const int*   src = (const int*)  d_in[2];
    const int*   dst = (const int*)  d_in[3];
    const float* wg  = (const float*)d_in[4];
    const float* wa  = (const float*)d_in[5];
    const float* wl  = (const float*)d_in[6];
    float* out = (float*)d_out;

    const int SMEM = (OUT_F * WROW + 8 * 2 * IN_DIM) * 4 + 8 * 32 * 16;  // ~55 KB
    cudaFuncSetAttribute(k_gather_out, cudaFuncAttributeMaxDynamicSharedMemorySize, SMEM);

    k_heavy<<<NODE_BLKS + (int)EDGE_BLKS, 256>>>(h, ef, wg, wa, dst);
    k_scan1<<<SCAN_NBLK, SCAN_BLK>>>();
    k_scan23<<<SCAN_NBLK, SCAN_BLK>>>();
    k_fill2<<<(N_EDGES / 2 + 255) / 256, 256>>>(src, dst);
    k_gather_out<<<592, 256, SMEM>>>(h, ef, wl, out);
}

// round 17
// speedup vs baseline: 1.0765x; 1.0765x over previous
#include <cuda_runtime.h>
#include <cuda_bf16.h>
#include <math_constants.h>

#define N_NODES 50000
#define N_EDGES 800000
#define NODE_DIM 64
#define EDGE_DIM 32
#define IN_DIM   160
#define OUT_F    64
#define WROW     164

#define SCAN_BLK 512
#define SCAN_NBLK ((N_NODES + SCAN_BLK - 1) / SCAN_BLK)   // 98
#define NODE_BLKS ((N_NODES + 7) / 8)                     // 6250
#define EDGE_BLKS (((size_t)N_EDGES * 4 + 255) / 256)     // 12500

// ---------------- static scratch (g_cnt kept zero between runs) ----------------
__device__ float g_pd[N_NODES];
__device__ float2 g_pc[N_NODES];        // (pd, cursor-as-int-bits): ONE sector in fill2
__device__ float2 g_sr[N_NODES];        // (sum exp(qe+pd) per src, h.wa[0:64])
__device__ int   g_cnt[N_NODES];        // ALWAYS zero at kernel_launch entry
__device__ int   g_off[N_NODES + 1];
__device__ int   g_aux[SCAN_NBLK];

__device__ float2 g_qt [N_EDGES];       // (ef.wg[0:32], ef.wa[64:96]) edge order
__device__ float4 g_meta[N_EDGES];      // (exp(qe+pd), te, src, eid) dst-sorted

// ---------------- packed f32x2 helpers ----------------
__device__ __forceinline__ unsigned long long fma2(unsigned long long a,
                                                   unsigned long long b,
                                                   unsigned long long c) {
    unsigned long long d;
    asm("fma.rn.f32x2 %0, %1, %2, %3;" : "=l"(d) : "l"(a), "l"(b), "l"(c));
    return d;
}
__device__ __forceinline__ unsigned long long pack2(float x, float y) {
    unsigned long long r;
    asm("mov.b64 %0, {%1, %2};" : "=l"(r) : "f"(x), "f"(y));
    return r;
}
__device__ __forceinline__ float2 unpack2(unsigned long long v) {
    float2 r;
    asm("mov.b64 {%0, %1}, %2;" : "=f"(r.x), "=f"(r.y) : "l"(v));
    return r;
}

// ---------------- K1: node dots+init ∥ ef dots + dst histogram (REDG) ------
__global__ void k_heavy(const float* __restrict__ h,
                        const float* __restrict__ ef,
                        const float* __restrict__ wg,
                        const float* __restrict__ wa,
                        const int* __restrict__ dst) {
    if (blockIdx.x < NODE_BLKS) {
        int node = blockIdx.x * 8 + (threadIdx.x >> 5);
        int lane = threadIdx.x & 31;
        if (node >= N_NODES) return;
        const float* hp = h + (size_t)node * NODE_DIM;
        float v0 = hp[lane];
        float v1 = hp[lane + 32];
        float pd = v0 * wg[96 + lane]  + v1 * wg[128 + lane];
        float r  = v0 * wa[lane]       + v1 * wa[32 + lane];
        #pragma unroll
        for (int o = 16; o; o >>= 1) {
            pd += __shfl_xor_sync(0xffffffffu, pd, o);
            r  += __shfl_xor_sync(0xffffffffu, r,  o);
        }
        if (lane == 0) {
            g_pd[node] = pd;
            g_sr[node] = make_float2(0.0f, r);
        }
    } else {
        int gid = (int)((blockIdx.x - NODE_BLKS) * blockDim.x + threadIdx.x);
        int e = gid >> 2;
        int k = gid & 3;
        if (e >= N_EDGES) return;
        float4 v0 = ((const float4*)ef)[(size_t)e * 8 + k];
        float4 v1 = ((const float4*)ef)[(size_t)e * 8 + k + 4];
        float4 a0 = ((const float4*)wg)[k];
        float4 a1 = ((const float4*)wg)[k + 4];
        float4 b0 = ((const float4*)wa)[16 + k];
        float4 b1 = ((const float4*)wa)[20 + k];
        float qe = v0.x * a0.x + v0.y * a0.y + v0.z * a0.z + v0.w * a0.w
                 + v1.x * a1.x + v1.y * a1.y + v1.z * a1.z + v1.w * a1.w;
        float te = v0.x * b0.x + v0.y * b0.y + v0.z * b0.z + v0.w * b0.w
                 + v1.x * b1.x + v1.y * b1.y + v1.z * b1.z + v1.w * b1.w;
        qe += __shfl_xor_sync(0xffffffffu, qe, 2);
        te += __shfl_xor_sync(0xffffffffu, te, 2);
        qe += __shfl_xor_sync(0xffffffffu, qe, 1);
        te += __shfl_xor_sync(0xffffffffu, te, 1);
        if (k == 0) {
            g_qt[e] = make_float2(qe, te);
            atomicAdd(&g_cnt[dst[e]], 1);     // no return -> REDG
        }
    }
}

// ---------------- K2a: per-block scan (zeroes g_cnt after reading) ---------
__global__ void k_scan1() {
    __shared__ int sh[SCAN_BLK];
    int tid = threadIdx.x;
    int i = blockIdx.x * SCAN_BLK + tid;
    int v = 0;
    if (i < N_NODES) {
        v = g_cnt[i];
        g_cnt[i] = 0;          // restore the zero invariant for the next run
    }
    sh[tid] = v;
    __syncthreads();
    #pragma unroll
    for (int off = 1; off < SCAN_BLK; off <<= 1) {
        int t = (tid >= off) ? sh[tid - off] : 0;
        __syncthreads();
        sh[tid] += t;
        __syncthreads();
    }
    if (i < N_NODES) g_off[i] = sh[tid] - v;
    if (tid == SCAN_BLK - 1) g_aux[blockIdx.x] = sh[tid];
}

// ---------------- K2b: aux prefix + final offsets + packed (pd,cur) --------
__global__ void k_scan23() {
    __shared__ int s_aux[SCAN_NBLK];
    __shared__ int s_base;
    int tid = threadIdx.x;
    if (tid < SCAN_NBLK) s_aux[tid] = g_aux[tid];
    __syncthreads();
    if (tid == 0) {
        int run = 0;
        for (int b = 0; b < blockIdx.x; b++) run += s_aux[b];
        s_base = run;
    }
    __syncthreads();
    int i = blockIdx.x * SCAN_BLK + tid;
    if (i < N_NODES) {
        int o = g_off[i] + s_base;
        g_off[i] = o;
        g_pc[i] = make_float2(g_pd[i], __int_as_float(o));   // pd + fill cursor
    }
    if (i == 0) g_off[N_NODES] = N_EDGES;
}

// ---------------- K3: light fill — 2 edges/thread, same-sector pd+cursor ---
__global__ void k_fill2(const int* __restrict__ src,
                        const int* __restrict__ dst) {
    int t = blockIdx.x * blockDim.x + threadIdx.x;
    int e0 = t * 2;
    if (e0 >= N_EDGES) return;
    float4 qt2 = ((const float4*)g_qt)[t];
    int2 s2 = ((const int2*)src)[t];
    int2 d2 = ((const int2*)dst)[t];
    // pd load and cursor atomic hit the SAME 8-byte struct (one L2 sector)
    float pd0 = g_pc[d2.x].x;
    float pd1 = g_pc[d2.y].x;
    float ee0 = __expf(qt2.x + pd0);
    float ee1 = __expf(qt2.z + pd1);
    atomicAdd(&g_sr[s2.x].x, ee0);
    atomicAdd(&g_sr[s2.y].x, ee1);
    int p0 = atomicAdd((int*)&g_pc[d2.x].y, 1);
    int p1 = atomicAdd((int*)&g_pc[d2.y].y, 1);
    g_meta[p0] = make_float4(ee0, qt2.y, __int_as_float(s2.x), __int_as_float(e0));
    g_meta[p1] = make_float4(ee1, qt2.w, __int_as_float(s2.y), __int_as_float(e0 + 1));
}

// ---------------- K4: gather (2 nodes/warp) + GEMV, 4 blocks/SM ------------
__global__ void __launch_bounds__(256, 4) k_gather_out(
        const float* __restrict__ h,
        const float* __restrict__ ef,
        const float* __restrict__ wlin,
        float* __restrict__ out) {
    extern __shared__ __align__(16) float smem[];
    float*  s_wT   = smem;                                  // [64][WROW] 42KB
    float*  s_hc   = smem + OUT_F * WROW;                   // [8][2][160] 10KB
    float4* s_meta = (float4*)(s_hc + 8 * 2 * IN_DIM);      // [8][32] 4KB

    int tid  = threadIdx.x;
    int warp = tid >> 5;
    int lane = tid & 31;
    int grp  = lane >> 4;       // 0/1: which edge of each 2-pack
    int hl   = lane & 15;       // position within 16-lane group

    for (int i = tid; i < IN_DIM * OUT_F; i += blockDim.x) {
        int k = i >> 6, c = i & 63;
        s_wT[c * WROW + k] = wlin[i];
    }
    __syncthreads();

    const ulonglong2*        h128 = (const ulonglong2*)h;           // 16 per row
    const unsigned long long* e64 = (const unsigned long long*)ef;  // 16 per row
    float*  hcW = s_hc + warp * (2 * IN_DIM);
    float4* mW  = s_meta + warp * 32;

    int gwarp  = blockIdx.x * 8 + warp;
    int nwarps = gridDim.x * 8;

    for (int g0 = gwarp * 2; g0 < N_NODES; g0 += nwarps * 2) {
        #pragma unroll
        for (int nn = 0; nn < 2; nn++) {
            int node = g0 + nn;
            if (node >= N_NODES) break;
            int beg = g_off[node];
            int end = g_off[node + 1];

            unsigned long long accHa = 0, accHb = 0;  // dims 4hl..4hl+3 (group partial)
            unsigned long long accE2 = 0;             // dims 2hl..2hl+1 (group partial)
            float se = 0.0f;

            for (int base = beg; base < end; base += 32) {
                int i = base + lane;
                if (i < end) {
                    float4 m4  = g_meta[i];         // contiguous LDG.128
                    int sidx   = __float_as_int(m4.z);
                    float2 sr  = g_sr[sidx];        // random, L2-resident
                    float gamma = m4.x / sr.x;
                    float w = __expf(sr.y + gamma * m4.y);
                    se += w;
                    mW[lane] = make_float4(w, w * gamma, m4.z, m4.w);
                }
                __syncwarp();
                int cnt  = min(32, end - base);
                int half = (cnt + 1) >> 1;
                #pragma unroll 4
                for (int t = 0; t < half; t++) {
                    int j = 2 * t + grp;
                    if (j < cnt) {
                        float4 m = mW[j];
                        int s  = __float_as_int(m.z);
                        int ej = __float_as_int(m.w);
                        ulonglong2 hv = __ldg(&h128[(size_t)s * 16 + hl]);   // LDG.128
                        unsigned long long ev = __ldg(&e64[(size_t)ej * 16 + hl]); // LDG.64
                        unsigned long long wpp = pack2(m.x, m.x);
                        accHa = fma2(wpp, hv.x, accHa);
                        accHb = fma2(wpp, hv.y, accHb);
                        accE2 = fma2(pack2(m.y, m.y), ev, accE2);
                    }
                }
                __syncwarp();
            }

            // reduce se over full warp
            #pragma unroll
            for (int o = 16; o; o >>= 1)
                se += __shfl_xor_sync(0xffffffffu, se, o);
            float inv = (end > beg) ? 1.0f / se : 0.0f;

            // combine the two 16-lane group partials
            float2 pa = unpack2(accHa), qa = unpack2(__shfl_xor_sync(0xffffffffu, accHa, 16));
            float2 pb = unpack2(accHb), qb = unpack2(__shfl_xor_sync(0xffffffffu, accHb, 16));
            float2 pe = unpack2(accE2), qe = unpack2(__shfl_xor_sync(0xffffffffu, accE2, 16));

            float* hc = hcW + nn * IN_DIM;
            float2 own = ((const float2*)h)[(size_t)node * 32 + lane];
            ((float2*)hc)[lane] = own;                                  // dims 0..63
            if (lane < 16) {
                ((float4*)(hc + 64))[hl] = make_float4((pa.x + qa.x) * inv,
                                                       (pa.y + qa.y) * inv,
                                                       (pb.x + qb.x) * inv,
                                                       (pb.y + qb.y) * inv); // 64..127
                ((float2*)(hc + 128))[hl] = make_float2((pe.x + qe.x) * inv,
                                                        (pe.y + qe.y) * inv); // 128..159
            }
        }
        __syncwarp();

        // ---- 2-node GEMV with packed FFMA2 ----
        unsigned long long aA[2][2] = {};
        unsigned long long aB[2][2] = {};
        const ulonglong2* wA = (const ulonglong2*)&s_wT[lane * WROW];
        const ulonglong2* wB = (const ulonglong2*)&s_wT[(lane + 32) * WROW];
        const ulonglong2* hv0 = (const ulonglong2*)(hcW + 0 * IN_DIM);
        const ulonglong2* hv1 = (const ulonglong2*)(hcW + 1 * IN_DIM);

        #pragma unroll 4
        for (int q = 0; q < IN_DIM / 4; q++) {
            ulonglong2 va = wA[q];
            ulonglong2 vb = wB[q];
            ulonglong2 x0 = hv0[q], x1 = hv1[q];
            aA[0][0] = fma2(va.x, x0.x, aA[0][0]); aA[0][1] = fma2(va.y, x0.y, aA[0][1]);
            aA[1][0] = fma2(va.x, x1.x, aA[1][0]); aA[1][1] = fma2(va.y, x1.y, aA[1][1]);
            aB[0][0] = fma2(vb.x, x0.x, aB[0][0]); aB[0][1] = fma2(vb.y, x0.y, aB[0][1]);
            aB[1][0] = fma2(vb.x, x1.x, aB[1][0]); aB[1][1] = fma2(vb.y, x1.y, aB[1][1]);
        }

        #pragma unroll
        for (int nn = 0; nn < 2; nn++) {
            int node = g0 + nn;
            if (node >= N_NODES) break;
            float2 uA0 = unpack2(aA[nn][0]), uA1 = unpack2(aA[nn][1]);
            float2 uB0 = unpack2(aB[nn][0]), uB1 = unpack2(aB[nn][1]);
            float oA = (uA0.x + uA0.y) + (uA1.x + uA1.y);
            float oB = (uB0.x + uB0.y) + (uB1.x + uB1.y);
            out[(size_t)node * OUT_F + lane]      = fmaxf(oA, 0.f);
            out[(size_t)node * OUT_F + 32 + lane] = fmaxf(oB, 0.f);
        }
        __syncwarp();
    }
}

// ---------------- launcher ----------------
extern "C" void kernel_launch(void* const* d_in, const int* in_sizes, int n_in,
                              void* d_out, int out_size) {
    const float* h   = (const float*)d_in[0];
    const float* ef  = (const float*)d_in[1];
    const int*   src = (const int*)  d_in[2];
    const int*   dst = (const int*)  d_in[3];
    const float* wg  = (const float*)d_in[4];
    const float* wa  = (const float*)d_in[5];
    const float* wl  = (const float*)d_in[6];
    float* out = (float*)d_out;

    const int SMEM = (OUT_F * WROW + 8 * 2 * IN_DIM) * 4 + 8 * 32 * 16;  // ~55 KB
    cudaFuncSetAttribute(k_gather_out, cudaFuncAttributeMaxDynamicSharedMemorySize, SMEM);

    k_heavy<<<NODE_BLKS + (int)EDGE_BLKS, 256>>>(h, ef, wg, wa, dst);
    k_scan1<<<SCAN_NBLK, SCAN_BLK>>>();
    k_scan23<<<SCAN_NBLK, SCAN_BLK>>>();
    k_fill2<<<(N_EDGES / 2 + 255) / 256, 256>>>(src, dst);
    k_gather_out<<<592, 256, SMEM>>>(h, ef, wl, out);
}